// round 8
// baseline (speedup 1.0000x reference)
#include <cuda_runtime.h>

// Problem dims
#define BB   64
#define SS   512
#define IDIM 128
#define HH   2048
#define OO   128

#define ALPHA_F 0.2f
#define OMA_F   0.8f      // 1 - alpha
#define SIG_F   0.005f

// Partition: 16 j-groups x 8 k-groups = 128 persistent CTAs
#define JG   16
#define KG   8
#define NCTA (JG*KG)      // 128  (<= 148 SMs, 1 CTA/SM -> all resident)
#define NJ   (HH/JG)      // 128 output columns per CTA
#define KS   (HH/KG)      // 256 k per CTA
#define IK   (IDIM/KG)    // 16  x-k per CTA

// SMEM strides (padded for conflict-free quad access)
#define WSP 260
#define HSP 260
#define WXP 20
#define XSP 20

// Scratch (static __device__ -> no allocations)
__device__ float g_Hall[(size_t)SS * BB * HH];   // [t][b][h]  268MB
__device__ float g_Part[(size_t)KG * BB * HH];   // [kg][b][j] 4MB
__device__ unsigned g_bar_cnt = 0;
__device__ volatile unsigned g_bar_gen = 0;

__device__ __forceinline__ unsigned f2tf32(float f) {
    unsigned u;
    asm("cvt.rna.tf32.f32 %0, %1;" : "=r"(u) : "f"(f));
    return u;
}

__device__ __forceinline__ void mma_tf32(float4& d,
    unsigned a0, unsigned a1, unsigned a2, unsigned a3,
    unsigned b0, unsigned b1) {
    asm volatile(
        "mma.sync.aligned.m16n8k8.row.col.f32.tf32.tf32.f32 "
        "{%0,%1,%2,%3}, {%4,%5,%6,%7}, {%8,%9}, {%0,%1,%2,%3};\n"
        : "+f"(d.x), "+f"(d.y), "+f"(d.z), "+f"(d.w)
        : "r"(a0), "r"(a1), "r"(a2), "r"(a3), "r"(b0), "r"(b1));
}

// Re-entrant sense-reversal grid barrier (persists safely across graph replays)
__device__ __forceinline__ void grid_barrier() {
    __syncthreads();
    if (threadIdx.x == 0) {
        __threadfence();
        unsigned gen = g_bar_gen;
        if (atomicAdd(&g_bar_cnt, 1u) == NCTA - 1) {
            g_bar_cnt = 0;
            __threadfence();
            g_bar_gen = gen + 1;
        } else {
            while (g_bar_gen == gen) { }
        }
        __threadfence();
    }
    __syncthreads();
}

__global__ void __launch_bounds__(256, 1) rnn_step_kernel(
    const float* __restrict__ x, const float* __restrict__ noise,
    const float* __restrict__ wi, const float* __restrict__ wrec,
    const float* __restrict__ g, const float* __restrict__ h0)
{
    extern __shared__ unsigned smem[];
    unsigned* ws  = smem;                 // NJ*WSP  : alpha*g[k]*wrec[j][k] (tf32)
    unsigned* hs  = ws  + NJ * WSP;       // BB*HSP  : h tile (tf32)
    unsigned* wxs = hs  + BB * HSP;       // NJ*WXP  : alpha*wi[i][j] (tf32)
    unsigned* xs  = wxs + NJ * WXP;       // BB*XSP  : x tile (tf32)

    const int tid  = threadIdx.x;
    const int lane = tid & 31;
    const int warp = tid >> 5;
    const int wm = warp >> 1, wn = warp & 1;
    const int m0 = wm * 16,   n0 = wn * 64;
    const int bid = blockIdx.x;
    const int jg = bid / KG, kg = bid % KG;

    // ---- load weight slices once, fold alpha*g ----
    for (int i4 = tid; i4 < NJ * KS / 4; i4 += 256) {
        int n  = i4 >> 6;            // KS/4 = 64 float4 per row
        int c4 = (i4 & 63) * 4;
        int jglob = jg * NJ + n;
        int kglob = kg * KS + c4;
        float4 w = *reinterpret_cast<const float4*>(wrec + (size_t)jglob * HH + kglob);
        uint4 u;
        u.x = f2tf32(ALPHA_F * g[kglob + 0] * w.x);
        u.y = f2tf32(ALPHA_F * g[kglob + 1] * w.y);
        u.z = f2tf32(ALPHA_F * g[kglob + 2] * w.z);
        u.w = f2tf32(ALPHA_F * g[kglob + 3] * w.w);
        *reinterpret_cast<uint4*>(ws + n * WSP + c4) = u;
    }
    for (int i = tid; i < NJ * IK; i += 256) {
        int n = i >> 4, c = i & 15;
        float v = wi[(size_t)(kg * IK + c) * HH + jg * NJ + n];
        wxs[n * WXP + c] = f2tf32(ALPHA_F * v);
    }

    // ---- init Hall[0] = broadcast(h0) ----
    for (int e = bid * 256 + tid; e < BB * HH; e += NCTA * 256) {
        g_Hall[e] = h0[e & (HH - 1)];
    }
    __threadfence();
    grid_barrier();

    const int ar_base = (m0 + (lane >> 2)) * HSP + (lane & 3);
    const int ax_base = (m0 + (lane >> 2)) * XSP + (lane & 3);

    for (int t = 1; t < SS; ++t) {
        // ---- stage h tile (fp32 -> tf32) ----
        const float* hsrc = g_Hall + (size_t)(t - 1) * BB * HH + kg * KS;
        for (int i4 = tid; i4 < BB * KS / 4; i4 += 256) {
            int b  = i4 >> 6;
            int c4 = (i4 & 63) * 4;
            float4 v = *reinterpret_cast<const float4*>(hsrc + (size_t)b * HH + c4);
            uint4 u;
            u.x = f2tf32(v.x); u.y = f2tf32(v.y); u.z = f2tf32(v.z); u.w = f2tf32(v.w);
            *reinterpret_cast<uint4*>(hs + b * HSP + c4) = u;
        }
        // ---- stage x tile ----
        const float* xsrc = x + (size_t)(t - 1) * IDIM + kg * IK;
        for (int i = tid; i < BB * IK; i += 256) {
            int b = i >> 4, c = i & 15;
            xs[b * XSP + c] = f2tf32(xsrc[(size_t)b * SS * IDIM + c]);
        }
        __syncthreads();

        // ---- phase 1: partial GEMM (64 x NJ over KS) + x-term ----
        float4 acc[8];
        #pragma unroll
        for (int nt = 0; nt < 8; nt++) acc[nt] = make_float4(0.f, 0.f, 0.f, 0.f);

        #pragma unroll 4
        for (int k = 0; k < KS; k += 8) {
            unsigned a0 = hs[ar_base + k];
            unsigned a1 = hs[ar_base + 8 * HSP + k];
            unsigned a2 = hs[ar_base + k + 4];
            unsigned a3 = hs[ar_base + 8 * HSP + k + 4];
            #pragma unroll
            for (int nt = 0; nt < 8; nt++) {
                int bo = (n0 + nt * 8 + (lane >> 2)) * WSP + k + (lane & 3);
                mma_tf32(acc[nt], a0, a1, a2, a3, ws[bo], ws[bo + 4]);
            }
        }
        #pragma unroll
        for (int k = 0; k < IK; k += 8) {
            unsigned a0 = xs[ax_base + k];
            unsigned a1 = xs[ax_base + 8 * XSP + k];
            unsigned a2 = xs[ax_base + k + 4];
            unsigned a3 = xs[ax_base + 8 * XSP + k + 4];
            #pragma unroll
            for (int nt = 0; nt < 8; nt++) {
                int bo = (n0 + nt * 8 + (lane >> 2)) * WXP + k + (lane & 3);
                mma_tf32(acc[nt], a0, a1, a2, a3, wxs[bo], wxs[bo + 4]);
            }
        }
        // store partials
        {
            int brow = m0 + (lane >> 2);
            #pragma unroll
            for (int nt = 0; nt < 8; nt++) {
                int jglob = jg * NJ + n0 + nt * 8 + (lane & 3) * 2;
                float* p0 = g_Part + ((size_t)kg * BB + brow) * HH + jglob;
                *reinterpret_cast<float2*>(p0)          = make_float2(acc[nt].x, acc[nt].y);
                *reinterpret_cast<float2*>(p0 + 8 * HH) = make_float2(acc[nt].z, acc[nt].w);
            }
        }
        __threadfence();
        grid_barrier();

        // ---- phase 2: combine partials + elementwise update ----
        {
            const float* hprev = g_Hall + (size_t)(t - 1) * BB * HH;
            float* hnew = g_Hall + (size_t)t * BB * HH;
            for (int i = tid; i < (BB / KG) * NJ; i += 256) {   // 8 x 128
                int b = kg * (BB / KG) + (i >> 7);
                int j = jg * NJ + (i & (NJ - 1));
                float s = OMA_F * hprev[(size_t)b * HH + j]
                        + SIG_F * noise[((size_t)b * SS + (t - 1)) * HH + j];
                #pragma unroll
                for (int p = 0; p < KG; p++)
                    s += g_Part[((size_t)p * BB + b) * HH + j];
                hnew[(size_t)b * HH + j] = s;
            }
        }
        __threadfence();
        grid_barrier();
    }
}

// out[b][t][:] = Hall[t][b][:] @ wout   — one big tf32 GEMM, 32768 x 128 x 2048
__global__ void __launch_bounds__(256) out_gemm_kernel(
    const float* __restrict__ wout, float* __restrict__ out)
{
    __shared__ unsigned As[128 * 36];
    __shared__ unsigned Bs[32 * 132];
    const int tid  = threadIdx.x;
    const int lane = tid & 31, warp = tid >> 5;
    const int wm = warp >> 1, wn = warp & 1;
    const int m0w = wm * 32, n0w = wn * 64;
    const int hr0 = blockIdx.x * 128;   // Hall flat row = t*64 + b

    float4 acc[2][8];
    #pragma unroll
    for (int mt = 0; mt < 2; mt++)
        #pragma unroll
        for (int nt = 0; nt < 8; nt++) acc[mt][nt] = make_float4(0.f, 0.f, 0.f, 0.f);

    for (int k0 = 0; k0 < HH; k0 += 32) {
        for (int i4 = tid; i4 < 1024; i4 += 256) {
            int r = i4 >> 3, c4 = (i4 & 7) * 4;
            float4 v = *reinterpret_cast<const float4*>(
                g_Hall + (size_t)(hr0 + r) * HH + k0 + c4);
            uint4 u;
            u.x = f2tf32(v.x); u.y = f2tf32(v.y); u.z = f2tf32(v.z); u.w = f2tf32(v.w);
            *reinterpret_cast<uint4*>(As + r * 36 + c4) = u;
        }
        for (int i4 = tid; i4 < 1024; i4 += 256) {
            int k = i4 >> 5, o4 = (i4 & 31) * 4;
            float4 v = *reinterpret_cast<const float4*>(wout + (size_t)(k0 + k) * OO + o4);
            uint4 u;
            u.x = f2tf32(v.x); u.y = f2tf32(v.y); u.z = f2tf32(v.z); u.w = f2tf32(v.w);
            *reinterpret_cast<uint4*>(Bs + k * 132 + o4) = u;
        }
        __syncthreads();
        #pragma unroll
        for (int kk = 0; kk < 32; kk += 8) {
            unsigned a[2][4];
            #pragma unroll
            for (int mt = 0; mt < 2; mt++) {
                int row = m0w + mt * 16 + (lane >> 2);
                a[mt][0] = As[row * 36 + kk + (lane & 3)];
                a[mt][1] = As[(row + 8) * 36 + kk + (lane & 3)];
                a[mt][2] = As[row * 36 + kk + 4 + (lane & 3)];
                a[mt][3] = As[(row + 8) * 36 + kk + 4 + (lane & 3)];
            }
            #pragma unroll
            for (int nt = 0; nt < 8; nt++) {
                int col = n0w + nt * 8 + (lane >> 2);
                unsigned b0 = Bs[(kk + (lane & 3)) * 132 + col];
                unsigned b1 = Bs[(kk + 4 + (lane & 3)) * 132 + col];
                mma_tf32(acc[0][nt], a[0][0], a[0][1], a[0][2], a[0][3], b0, b1);
                mma_tf32(acc[1][nt], a[1][0], a[1][1], a[1][2], a[1][3], b0, b1);
            }
        }
        __syncthreads();
    }
    // write: Hall row hr = t*64+b  ->  out row b*512+t
    #pragma unroll
    for (int mt = 0; mt < 2; mt++) {
        int hr = hr0 + m0w + mt * 16 + (lane >> 2);
        #pragma unroll
        for (int half = 0; half < 2; half++) {
            int hrr = hr + half * 8;
            int b = hrr & (BB - 1), tt = hrr >> 6;
            float* orow = out + ((size_t)b * SS + tt) * OO;
            #pragma unroll
            for (int nt = 0; nt < 8; nt++) {
                int col = n0w + nt * 8 + (lane & 3) * 2;
                float2 v = half ? make_float2(acc[mt][nt].z, acc[mt][nt].w)
                                : make_float2(acc[mt][nt].x, acc[mt][nt].y);
                *reinterpret_cast<float2*>(orow + col) = v;
            }
        }
    }
}

extern "C" void kernel_launch(void* const* d_in, const int* in_sizes, int n_in,
                              void* d_out, int out_size) {
    const float* x     = (const float*)d_in[0];
    const float* noise = (const float*)d_in[1];
    const float* wi    = (const float*)d_in[2];
    const float* wrec  = (const float*)d_in[3];
    const float* wout  = (const float*)d_in[4];
    const float* g     = (const float*)d_in[5];
    const float* h0    = (const float*)d_in[6];
    float* out = (float*)d_out;

    size_t smem = (size_t)(NJ * WSP + BB * HSP + NJ * WXP + BB * XSP) * 4;  // 215040 B
    cudaFuncSetAttribute(rnn_step_kernel,
                         cudaFuncAttributeMaxDynamicSharedMemorySize, (int)smem);

    rnn_step_kernel<<<NCTA, 256, smem>>>(x, noise, wi, wrec, g, h0);
    out_gemm_kernel<<<(BB * SS) / 128, 256>>>(wout, out);
}

// round 12
// speedup vs baseline: 1.1182x; 1.1182x over previous
#include <cuda_runtime.h>

// Problem dims
#define BB   64
#define SS   512
#define IDIM 128
#define HH   2048
#define OO   128

#define ALPHA_F 0.2f
#define OMA_F   0.8f      // 1 - alpha
#define SIG_F   0.005f

// Partition: 16 j-groups x 8 k-groups = 128 persistent CTAs (1 per SM)
#define JG   16
#define KG   8
#define NCTA (JG*KG)      // 128
#define NJ   (HH/JG)      // 128 output columns per CTA
#define KS   (HH/KG)      // 256 k per CTA
#define IK   (IDIM/KG)    // 16  x-k per CTA

// SMEM strides (padded for conflict-free access)
#define WSP 260
#define HSP 260
#define WXP 20
#define XSP 20

#define NFLAG (SS*NCTA)

// Scratch (static __device__ -> no allocations)
__device__ float g_Hall[(size_t)SS * BB * HH];   // [t][b][h]  268MB
__device__ float g_Part[(size_t)KG * BB * HH];   // [kg][b][j] 4MB
__device__ unsigned g_pflag[NFLAG];              // partials ready, per (t, jg, kg)
__device__ unsigned g_hflag[NFLAG];              // hnew slice ready, per (t, jg, kg)
__device__ unsigned g_bar_cnt = 0;
__device__ volatile unsigned g_bar_gen = 0;

__device__ __forceinline__ unsigned f2tf32(float f) {
    unsigned u;
    asm("cvt.rna.tf32.f32 %0, %1;" : "=r"(u) : "f"(f));
    return u;
}

__device__ __forceinline__ unsigned ld_acq(const unsigned* p) {
    unsigned v;
    asm volatile("ld.global.acquire.gpu.b32 %0, [%1];" : "=r"(v) : "l"(p));
    return v;
}
__device__ __forceinline__ void st_rel(unsigned* p, unsigned v) {
    asm volatile("st.global.release.gpu.b32 [%0], %1;" :: "l"(p), "r"(v));
}

__device__ __forceinline__ void mma_tf32(float4& d,
    unsigned a0, unsigned a1, unsigned a2, unsigned a3,
    unsigned b0, unsigned b1) {
    asm volatile(
        "mma.sync.aligned.m16n8k8.row.col.f32.tf32.tf32.f32 "
        "{%0,%1,%2,%3}, {%4,%5,%6,%7}, {%8,%9}, {%0,%1,%2,%3};\n"
        : "+f"(d.x), "+f"(d.y), "+f"(d.z), "+f"(d.w)
        : "r"(a0), "r"(a1), "r"(a2), "r"(a3), "r"(b0), "r"(b1));
}

// Re-entrant sense-reversal grid barrier (prologue only)
__device__ __forceinline__ void grid_barrier() {
    __syncthreads();
    if (threadIdx.x == 0) {
        __threadfence();
        unsigned gen = g_bar_gen;
        if (atomicAdd(&g_bar_cnt, 1u) == NCTA - 1) {
            g_bar_cnt = 0;
            __threadfence();
            g_bar_gen = gen + 1;
        } else {
            while (g_bar_gen == gen) { }
        }
        __threadfence();
    }
    __syncthreads();
}

__global__ void __launch_bounds__(256, 1) rnn_step_kernel(
    const float* __restrict__ x, const float* __restrict__ noise,
    const float* __restrict__ wi, const float* __restrict__ wrec,
    const float* __restrict__ g, const float* __restrict__ h0)
{
    extern __shared__ unsigned smem[];
    unsigned* ws  = smem;                 // NJ*WSP  : alpha*g[k]*wrec[j][k] (tf32)
    unsigned* hs  = ws  + NJ * WSP;       // BB*HSP  : h tile (tf32)
    unsigned* wxs = hs  + BB * HSP;       // NJ*WXP  : alpha*wi[i][j] (tf32)
    unsigned* xs  = wxs + NJ * WXP;       // BB*XSP  : x tile (tf32)

    const int tid  = threadIdx.x;
    const int lane = tid & 31;
    const int warp = tid >> 5;
    const int wm = warp >> 2, wn = warp & 3;     // 2 x 4 warp grid
    const int m0 = wm * 32,   n0 = wn * 32;      // 32x32 per warp
    const int lr = lane >> 2, lc = lane & 3;
    const int bid = blockIdx.x;
    const int jg = bid / KG, kg = bid % KG;

    // ---- load weight slices once, fold alpha*g ----
    for (int i4 = tid; i4 < NJ * KS / 4; i4 += 256) {
        int n  = i4 >> 6;            // KS/4 = 64 float4 per row
        int c4 = (i4 & 63) * 4;
        int jglob = jg * NJ + n;
        int kglob = kg * KS + c4;
        float4 w = *reinterpret_cast<const float4*>(wrec + (size_t)jglob * HH + kglob);
        uint4 u;
        u.x = f2tf32(ALPHA_F * g[kglob + 0] * w.x);
        u.y = f2tf32(ALPHA_F * g[kglob + 1] * w.y);
        u.z = f2tf32(ALPHA_F * g[kglob + 2] * w.z);
        u.w = f2tf32(ALPHA_F * g[kglob + 3] * w.w);
        *reinterpret_cast<uint4*>(ws + n * WSP + c4) = u;
    }
    for (int i = tid; i < NJ * IK; i += 256) {
        int n = i >> 4, c = i & 15;
        float v = wi[(size_t)(kg * IK + c) * HH + jg * NJ + n];
        wxs[n * WXP + c] = f2tf32(ALPHA_F * v);
    }

    // ---- zero sync flags (graph replays reuse device globals) ----
    for (int e = bid * 256 + tid; e < NFLAG; e += NCTA * 256) {
        g_pflag[e] = 0;
        g_hflag[e] = 0;
    }
    // ---- init Hall[0] = broadcast(h0) ----
    for (int e = bid * 256 + tid; e < BB * HH; e += NCTA * 256) {
        g_Hall[e] = h0[e & (HH - 1)];
    }
    __threadfence();
    grid_barrier();   // the ONLY grid barrier

    // producer clusters this CTA consumes h-columns from, plus own cluster
    // (own cluster's hflags certify all readers of our step-(t-1) partials are done)
    const int wait_cl0 = 2 * kg, wait_cl1 = 2 * kg + 1, wait_cl2 = jg;

    for (int t = 1; t < SS; ++t) {
        // ---- stage x tile (independent of h) ----
        const float* xsrc = x + (size_t)(t - 1) * IDIM + kg * IK;
        for (int i = tid; i < BB * IK; i += 256) {
            int b = i >> 4, c = i & 15;
            xs[b * XSP + c] = f2tf32(xsrc[(size_t)b * SS * IDIM + c]);
        }
        __syncthreads();

        float4 acc[2][4];
        #pragma unroll
        for (int mt = 0; mt < 2; mt++)
            #pragma unroll
            for (int nt = 0; nt < 4; nt++) acc[mt][nt] = make_float4(0.f, 0.f, 0.f, 0.f);

        // ---- x-term MMAs while h may still be in flight ----
        #pragma unroll
        for (int k = 0; k < IK; k += 8) {
            unsigned a0[2], a1[2], a2[2], a3[2];
            #pragma unroll
            for (int mt = 0; mt < 2; mt++) {
                int ab = (m0 + mt * 16 + lr) * XSP + lc + k;
                a0[mt] = xs[ab];            a1[mt] = xs[ab + 8 * XSP];
                a2[mt] = xs[ab + 4];        a3[mt] = xs[ab + 8 * XSP + 4];
            }
            #pragma unroll
            for (int nt = 0; nt < 4; nt++) {
                int bo = (n0 + nt * 8 + lr) * WXP + k + lc;
                unsigned b0 = wxs[bo], b1 = wxs[bo + 4];
                mma_tf32(acc[0][nt], a0[0], a1[0], a2[0], a3[0], b0, b1);
                mma_tf32(acc[1][nt], a0[1], a1[1], a2[1], a3[1], b0, b1);
            }
        }

        // ---- wait for producer hnew slices (t>=2; t==1 guarded by barrier) ----
        if (t >= 2 && warp == 0 && lane < 24) {
            int cl = (lane < 8) ? wait_cl0 : (lane < 16) ? wait_cl1 : wait_cl2;
            const unsigned* f = g_hflag + (size_t)(t - 1) * NCTA + cl * KG + (lane & 7);
            while (ld_acq(f) == 0) { }
        }
        __syncthreads();

        // ---- stage h tile (fp32 -> tf32) ----
        const float* hsrc = g_Hall + (size_t)(t - 1) * BB * HH + kg * KS;
        for (int i4 = tid; i4 < BB * KS / 4; i4 += 256) {
            int b  = i4 >> 6;
            int c4 = (i4 & 63) * 4;
            float4 v = *reinterpret_cast<const float4*>(hsrc + (size_t)b * HH + c4);
            uint4 u;
            u.x = f2tf32(v.x); u.y = f2tf32(v.y); u.z = f2tf32(v.z); u.w = f2tf32(v.w);
            *reinterpret_cast<uint4*>(hs + b * HSP + c4) = u;
        }
        __syncthreads();

        // ---- main recurrent partial GEMM (64 x 128 over KS=256) ----
        #pragma unroll 2
        for (int k = 0; k < KS; k += 8) {
            unsigned a0[2], a1[2], a2[2], a3[2];
            #pragma unroll
            for (int mt = 0; mt < 2; mt++) {
                int ab = (m0 + mt * 16 + lr) * HSP + lc + k;
                a0[mt] = hs[ab];            a1[mt] = hs[ab + 8 * HSP];
                a2[mt] = hs[ab + 4];        a3[mt] = hs[ab + 8 * HSP + 4];
            }
            #pragma unroll
            for (int nt = 0; nt < 4; nt++) {
                int bo = (n0 + nt * 8 + lr) * WSP + k + lc;
                unsigned b0 = ws[bo], b1 = ws[bo + 4];
                mma_tf32(acc[0][nt], a0[0], a1[0], a2[0], a3[0], b0, b1);
                mma_tf32(acc[1][nt], a0[1], a1[1], a2[1], a3[1], b0, b1);
            }
        }

        // ---- store partials ----
        #pragma unroll
        for (int mt = 0; mt < 2; mt++) {
            int brow = m0 + mt * 16 + lr;
            #pragma unroll
            for (int nt = 0; nt < 4; nt++) {
                int jglob = jg * NJ + n0 + nt * 8 + lc * 2;
                float* p0 = g_Part + ((size_t)kg * BB + brow) * HH + jglob;
                *reinterpret_cast<float2*>(p0)          = make_float2(acc[mt][nt].x, acc[mt][nt].y);
                *reinterpret_cast<float2*>(p0 + 8 * HH) = make_float2(acc[mt][nt].z, acc[mt][nt].w);
            }
        }
        if (tid == 0) st_rel(g_pflag + (size_t)t * NCTA + jg * KG + kg, 1u);

        // ---- wait all 8 partials of this j-cluster ----
        if (warp == 0 && lane < KG) {
            const unsigned* f = g_pflag + (size_t)t * NCTA + jg * KG + lane;
            while (ld_acq(f) == 0) { }
        }
        __syncthreads();

        // ---- phase 2: combine partials + elementwise update ----
        {
            const float* hprev = g_Hall + (size_t)(t - 1) * BB * HH;
            float* hnew = g_Hall + (size_t)t * BB * HH;
            for (int i = tid; i < (BB / KG) * NJ; i += 256) {   // 8 rows x 128 cols
                int b = kg * (BB / KG) + (i >> 7);
                int j = jg * NJ + (i & (NJ - 1));
                float s = OMA_F * hprev[(size_t)b * HH + j]
                        + SIG_F * noise[((size_t)b * SS + (t - 1)) * HH + j];
                #pragma unroll
                for (int p = 0; p < KG; p++)
                    s += g_Part[((size_t)p * BB + b) * HH + j];
                hnew[(size_t)b * HH + j] = s;
            }
        }
        __syncthreads();
        if (tid == 0) st_rel(g_hflag + (size_t)t * NCTA + jg * KG + kg, 1u);
    }
}

// out[b][t][:] = Hall[t][b][:] @ wout   — one big tf32 GEMM, 32768 x 128 x 2048
__global__ void __launch_bounds__(256) out_gemm_kernel(
    const float* __restrict__ wout, float* __restrict__ out)
{
    __shared__ unsigned As[128 * 36];
    __shared__ unsigned Bs[32 * 132];
    const int tid  = threadIdx.x;
    const int lane = tid & 31, warp = tid >> 5;
    const int wm = warp >> 1, wn = warp & 1;
    const int m0w = wm * 32, n0w = wn * 64;
    const int hr0 = blockIdx.x * 128;   // Hall flat row = t*64 + b

    float4 acc[2][8];
    #pragma unroll
    for (int mt = 0; mt < 2; mt++)
        #pragma unroll
        for (int nt = 0; nt < 8; nt++) acc[mt][nt] = make_float4(0.f, 0.f, 0.f, 0.f);

    for (int k0 = 0; k0 < HH; k0 += 32) {
        for (int i4 = tid; i4 < 1024; i4 += 256) {
            int r = i4 >> 3, c4 = (i4 & 7) * 4;
            float4 v = *reinterpret_cast<const float4*>(
                g_Hall + (size_t)(hr0 + r) * HH + k0 + c4);
            uint4 u;
            u.x = f2tf32(v.x); u.y = f2tf32(v.y); u.z = f2tf32(v.z); u.w = f2tf32(v.w);
            *reinterpret_cast<uint4*>(As + r * 36 + c4) = u;
        }
        for (int i4 = tid; i4 < 1024; i4 += 256) {
            int k = i4 >> 5, o4 = (i4 & 31) * 4;
            float4 v = *reinterpret_cast<const float4*>(wout + (size_t)(k0 + k) * OO + o4);
            uint4 u;
            u.x = f2tf32(v.x); u.y = f2tf32(v.y); u.z = f2tf32(v.z); u.w = f2tf32(v.w);
            *reinterpret_cast<uint4*>(Bs + k * 132 + o4) = u;
        }
        __syncthreads();
        #pragma unroll
        for (int kk = 0; kk < 32; kk += 8) {
            unsigned a[2][4];
            #pragma unroll
            for (int mt = 0; mt < 2; mt++) {
                int row = m0w + mt * 16 + (lane >> 2);
                a[mt][0] = As[row * 36 + kk + (lane & 3)];
                a[mt][1] = As[(row + 8) * 36 + kk + (lane & 3)];
                a[mt][2] = As[row * 36 + kk + 4 + (lane & 3)];
                a[mt][3] = As[(row + 8) * 36 + kk + 4 + (lane & 3)];
            }
            #pragma unroll
            for (int nt = 0; nt < 8; nt++) {
                int col = n0w + nt * 8 + (lane >> 2);
                unsigned b0 = Bs[(kk + (lane & 3)) * 132 + col];
                unsigned b1 = Bs[(kk + 4 + (lane & 3)) * 132 + col];
                mma_tf32(acc[0][nt], a[0][0], a[0][1], a[0][2], a[0][3], b0, b1);
                mma_tf32(acc[1][nt], a[1][0], a[1][1], a[1][2], a[1][3], b0, b1);
            }
        }
        __syncthreads();
    }
    // write: Hall row hr = t*64+b  ->  out row b*512+t
    #pragma unroll
    for (int mt = 0; mt < 2; mt++) {
        int hr = hr0 + m0w + mt * 16 + (lane >> 2);
        #pragma unroll
        for (int half = 0; half < 2; half++) {
            int hrr = hr + half * 8;
            int b = hrr & (BB - 1), tt = hrr >> 6;
            float* orow = out + ((size_t)b * SS + tt) * OO;
            #pragma unroll
            for (int nt = 0; nt < 8; nt++) {
                int col = n0w + nt * 8 + (lane & 3) * 2;
                float2 v = half ? make_float2(acc[mt][nt].z, acc[mt][nt].w)
                                : make_float2(acc[mt][nt].x, acc[mt][nt].y);
                *reinterpret_cast<float2*>(orow + col) = v;
            }
        }
    }
}

extern "C" void kernel_launch(void* const* d_in, const int* in_sizes, int n_in,
                              void* d_out, int out_size) {
    const float* x     = (const float*)d_in[0];
    const float* noise = (const float*)d_in[1];
    const float* wi    = (const float*)d_in[2];
    const float* wrec  = (const float*)d_in[3];
    const float* wout  = (const float*)d_in[4];
    const float* g     = (const float*)d_in[5];
    const float* h0    = (const float*)d_in[6];
    float* out = (float*)d_out;

    size_t smem = (size_t)(NJ * WSP + BB * HSP + NJ * WXP + BB * XSP) * 4;  // 215040 B
    cudaFuncSetAttribute(rnn_step_kernel,
                         cudaFuncAttributeMaxDynamicSharedMemorySize, (int)smem);

    rnn_step_kernel<<<NCTA, 256, smem>>>(x, noise, wi, wrec, g, h0);
    out_gemm_kernel<<<(BB * SS) / 128, 256>>>(wout, out);
}

// round 13
// speedup vs baseline: 1.2499x; 1.1178x over previous
#include <cuda_runtime.h>

// Problem dims
#define BB   64
#define SS   512
#define IDIM 128
#define HH   2048
#define OO   128

#define ALPHA_F 0.2f
#define OMA_F   0.8f      // 1 - alpha
#define SIG_F   0.005f

// Partition: 16 j-groups x 8 k-groups = 128 persistent CTAs (1 per SM)
#define JG   16
#define KG   8
#define NCTA (JG*KG)      // 128
#define NJ   (HH/JG)      // 128 output columns per CTA
#define KS   (HH/KG)      // 256 k per CTA
#define IK   (IDIM/KG)    // 16  x-k per CTA

// SMEM strides (padded for conflict-free access)
#define WSP 260
#define HSP 260
#define WXP 20
#define XSP 20
#define PSP 132           // partial repack row stride (floats), 16B-aligned rows

#define NFLAG (SS*NCTA)

// Scratch (static __device__ -> no allocations)
__device__ float g_Hall[(size_t)SS * BB * HH];   // [t][b][h]  268MB
__device__ float g_Part[(size_t)KG * BB * HH];   // [kg][b][j] 4MB
__device__ unsigned g_pflag[NFLAG];              // partials ready, per (t, jg, kg)
__device__ unsigned g_hflag[NFLAG];              // hnew slice ready, per (t, jg, kg)
__device__ unsigned g_bar_cnt = 0;
__device__ volatile unsigned g_bar_gen = 0;

__device__ __forceinline__ unsigned f2tf32(float f) {
    unsigned u;
    asm("cvt.rna.tf32.f32 %0, %1;" : "=r"(u) : "f"(f));
    return u;
}

__device__ __forceinline__ unsigned ld_acq(const unsigned* p) {
    unsigned v;
    asm volatile("ld.global.acquire.gpu.b32 %0, [%1];" : "=r"(v) : "l"(p));
    return v;
}
__device__ __forceinline__ void st_rel(unsigned* p, unsigned v) {
    asm volatile("st.global.release.gpu.b32 [%0], %1;" :: "l"(p), "r"(v));
}

__device__ __forceinline__ void mma_tf32(float4& d,
    unsigned a0, unsigned a1, unsigned a2, unsigned a3,
    unsigned b0, unsigned b1) {
    asm volatile(
        "mma.sync.aligned.m16n8k8.row.col.f32.tf32.tf32.f32 "
        "{%0,%1,%2,%3}, {%4,%5,%6,%7}, {%8,%9}, {%0,%1,%2,%3};\n"
        : "+f"(d.x), "+f"(d.y), "+f"(d.z), "+f"(d.w)
        : "r"(a0), "r"(a1), "r"(a2), "r"(a3), "r"(b0), "r"(b1));
}

// Re-entrant sense-reversal grid barrier (prologue only)
__device__ __forceinline__ void grid_barrier() {
    __syncthreads();
    if (threadIdx.x == 0) {
        __threadfence();
        unsigned gen = g_bar_gen;
        if (atomicAdd(&g_bar_cnt, 1u) == NCTA - 1) {
            g_bar_cnt = 0;
            __threadfence();
            g_bar_gen = gen + 1;
        } else {
            while (g_bar_gen == gen) { }
        }
        __threadfence();
    }
    __syncthreads();
}

__global__ void __launch_bounds__(256, 1) rnn_step_kernel(
    const float* __restrict__ x, const float* __restrict__ noise,
    const float* __restrict__ wi, const float* __restrict__ wrec,
    const float* __restrict__ g, const float* __restrict__ h0)
{
    extern __shared__ unsigned smem[];
    unsigned* ws  = smem;                 // NJ*WSP  : alpha*g[k]*wrec[j][k] (tf32)
    unsigned* hs  = ws  + NJ * WSP;       // BB*HSP  : h tile (tf32) / partial repack
    unsigned* wxs = hs  + BB * HSP;       // NJ*WXP  : alpha*wi[i][j] (tf32)
    unsigned* xs  = wxs + NJ * WXP;       // BB*XSP  : x tile (tf32)
    float*    ps  = reinterpret_cast<float*>(hs);   // reuse hs: 64 x PSP partial repack

    const int tid  = threadIdx.x;
    const int lane = tid & 31;
    const int warp = tid >> 5;
    const int wm = warp >> 2, wn = warp & 3;     // 2 x 4 warp grid
    const int m0 = wm * 32,   n0 = wn * 32;      // 32x32 per warp
    const int lr = lane >> 2, lc = lane & 3;
    const int bid = blockIdx.x;
    const int jg = bid / KG, kg = bid % KG;

    // ---- load weight slices once, fold alpha*g ----
    for (int i4 = tid; i4 < NJ * KS / 4; i4 += 256) {
        int n  = i4 >> 6;            // KS/4 = 64 float4 per row
        int c4 = (i4 & 63) * 4;
        int jglob = jg * NJ + n;
        int kglob = kg * KS + c4;
        float4 w = *reinterpret_cast<const float4*>(wrec + (size_t)jglob * HH + kglob);
        uint4 u;
        u.x = f2tf32(ALPHA_F * g[kglob + 0] * w.x);
        u.y = f2tf32(ALPHA_F * g[kglob + 1] * w.y);
        u.z = f2tf32(ALPHA_F * g[kglob + 2] * w.z);
        u.w = f2tf32(ALPHA_F * g[kglob + 3] * w.w);
        *reinterpret_cast<uint4*>(ws + n * WSP + c4) = u;
    }
    for (int i = tid; i < NJ * IK; i += 256) {
        int n = i >> 4, c = i & 15;
        float v = wi[(size_t)(kg * IK + c) * HH + jg * NJ + n];
        wxs[n * WXP + c] = f2tf32(ALPHA_F * v);
    }

    // ---- zero sync flags (graph replays reuse device globals) ----
    for (int e = bid * 256 + tid; e < NFLAG; e += NCTA * 256) {
        g_pflag[e] = 0;
        g_hflag[e] = 0;
    }
    // ---- init Hall[0] = broadcast(h0) ----
    for (int e = bid * 256 + tid; e < BB * HH; e += NCTA * 256) {
        g_Hall[e] = h0[e & (HH - 1)];
    }
    __threadfence();
    grid_barrier();   // the ONLY grid barrier

    // producer clusters this CTA consumes h-columns from, plus own cluster
    const int wait_cl0 = 2 * kg, wait_cl1 = 2 * kg + 1, wait_cl2 = jg;

    // phase-2 fixed per-thread coordinates (one float4 each)
    const int p2_b = kg * (BB / KG) + (tid >> 5);
    const int p2_j = jg * NJ + (tid & 31) * 4;
    const size_t p2_off = (size_t)p2_b * HH + p2_j;

    for (int t = 1; t < SS; ++t) {
        // ---- stage x tile (float4, independent of h) ----
        {
            // 256 float4 = BB*IK; one per thread
            int b = tid >> 2, c4 = (tid & 3) * 4;
            const float* xsrc = x + ((size_t)b * SS + (t - 1)) * IDIM + kg * IK + c4;
            float4 v = *reinterpret_cast<const float4*>(xsrc);
            uint4 u;
            u.x = f2tf32(v.x); u.y = f2tf32(v.y); u.z = f2tf32(v.z); u.w = f2tf32(v.w);
            *reinterpret_cast<uint4*>(xs + b * XSP + c4) = u;
        }
        __syncthreads();

        float4 acc[2][4];
        #pragma unroll
        for (int mt = 0; mt < 2; mt++)
            #pragma unroll
            for (int nt = 0; nt < 4; nt++) acc[mt][nt] = make_float4(0.f, 0.f, 0.f, 0.f);

        // ---- x-term MMAs while h may still be in flight ----
        #pragma unroll
        for (int k = 0; k < IK; k += 8) {
            unsigned a0[2], a1[2], a2[2], a3[2];
            #pragma unroll
            for (int mt = 0; mt < 2; mt++) {
                int ab = (m0 + mt * 16 + lr) * XSP + lc + k;
                a0[mt] = xs[ab];            a1[mt] = xs[ab + 8 * XSP];
                a2[mt] = xs[ab + 4];        a3[mt] = xs[ab + 8 * XSP + 4];
            }
            #pragma unroll
            for (int nt = 0; nt < 4; nt++) {
                int bo = (n0 + nt * 8 + lr) * WXP + k + lc;
                unsigned b0 = wxs[bo], b1 = wxs[bo + 4];
                mma_tf32(acc[0][nt], a0[0], a1[0], a2[0], a3[0], b0, b1);
                mma_tf32(acc[1][nt], a0[1], a1[1], a2[1], a3[1], b0, b1);
            }
        }

        // ---- wait for producer hnew slices (t>=2; t==1 guarded by barrier) ----
        if (t >= 2 && warp == 0 && lane < 24) {
            int cl = (lane < 8) ? wait_cl0 : (lane < 16) ? wait_cl1 : wait_cl2;
            const unsigned* f = g_hflag + (size_t)(t - 1) * NCTA + cl * KG + (lane & 7);
            while (ld_acq(f) == 0) { }
        }
        __syncthreads();

        // ---- stage h tile (fp32 -> tf32, float4) ----
        const float* hsrc = g_Hall + (size_t)(t - 1) * BB * HH + kg * KS;
        for (int i4 = tid; i4 < BB * KS / 4; i4 += 256) {
            int b  = i4 >> 6;
            int c4 = (i4 & 63) * 4;
            float4 v = *reinterpret_cast<const float4*>(hsrc + (size_t)b * HH + c4);
            uint4 u;
            u.x = f2tf32(v.x); u.y = f2tf32(v.y); u.z = f2tf32(v.z); u.w = f2tf32(v.w);
            *reinterpret_cast<uint4*>(hs + b * HSP + c4) = u;
        }
        __syncthreads();

        // ---- main recurrent partial GEMM (64 x 128 over KS=256) ----
        #pragma unroll 2
        for (int k = 0; k < KS; k += 8) {
            unsigned a0[2], a1[2], a2[2], a3[2];
            #pragma unroll
            for (int mt = 0; mt < 2; mt++) {
                int ab = (m0 + mt * 16 + lr) * HSP + lc + k;
                a0[mt] = hs[ab];            a1[mt] = hs[ab + 8 * HSP];
                a2[mt] = hs[ab + 4];        a3[mt] = hs[ab + 8 * HSP + 4];
            }
            #pragma unroll
            for (int nt = 0; nt < 4; nt++) {
                int bo = (n0 + nt * 8 + lr) * WSP + k + lc;
                unsigned b0 = ws[bo], b1 = ws[bo + 4];
                mma_tf32(acc[0][nt], a0[0], a1[0], a2[0], a3[0], b0, b1);
                mma_tf32(acc[1][nt], a0[1], a1[1], a2[1], a3[1], b0, b1);
            }
        }
        __syncthreads();   // hs (A tile) dead; safe to repack partials into it

        // ---- repack fragments into smem (MIO pipe), then vector STG ----
        #pragma unroll
        for (int mt = 0; mt < 2; mt++) {
            int brow = m0 + mt * 16 + lr;
            #pragma unroll
            for (int nt = 0; nt < 4; nt++) {
                int jloc = n0 + nt * 8 + lc * 2;
                *reinterpret_cast<float2*>(ps + brow * PSP + jloc)
                    = make_float2(acc[mt][nt].x, acc[mt][nt].y);
                *reinterpret_cast<float2*>(ps + (brow + 8) * PSP + jloc)
                    = make_float2(acc[mt][nt].z, acc[mt][nt].w);
            }
        }
        __syncthreads();
        {
            // 2048 float4 = 64 x 128; 8 per thread
            #pragma unroll
            for (int i = 0; i < 8; i++) {
                int idx = tid + i * 256;
                int row = idx >> 5, c4 = (idx & 31) * 4;
                float4 v = *reinterpret_cast<const float4*>(ps + row * PSP + c4);
                *reinterpret_cast<float4*>(
                    g_Part + ((size_t)kg * BB + row) * HH + jg * NJ + c4) = v;
            }
        }
        __syncthreads();   // all threads' partial STGs happen-before the release
        if (tid == 0) st_rel(g_pflag + (size_t)t * NCTA + jg * KG + kg, 1u);

        // ---- wait all 8 partials of this j-cluster ----
        if (warp == 0 && lane < KG) {
            const unsigned* f = g_pflag + (size_t)t * NCTA + jg * KG + lane;
            while (ld_acq(f) == 0) { }
        }
        __syncthreads();

        // ---- phase 2: combine partials + elementwise update (all float4) ----
        {
            const float* hprev = g_Hall + (size_t)(t - 1) * BB * HH;
            float* hnew = g_Hall + (size_t)t * BB * HH;
            float4 hp = *reinterpret_cast<const float4*>(hprev + p2_off);
            float4 nz = *reinterpret_cast<const float4*>(
                noise + ((size_t)p2_b * SS + (t - 1)) * HH + p2_j);
            float4 s;
            s.x = OMA_F * hp.x + SIG_F * nz.x;
            s.y = OMA_F * hp.y + SIG_F * nz.y;
            s.z = OMA_F * hp.z + SIG_F * nz.z;
            s.w = OMA_F * hp.w + SIG_F * nz.w;
            #pragma unroll
            for (int p = 0; p < KG; p++) {
                float4 pv = *reinterpret_cast<const float4*>(
                    g_Part + ((size_t)p * BB + p2_b) * HH + p2_j);
                s.x += pv.x; s.y += pv.y; s.z += pv.z; s.w += pv.w;
            }
            *reinterpret_cast<float4*>(hnew + p2_off) = s;
        }
        __syncthreads();
        if (tid == 0) st_rel(g_hflag + (size_t)t * NCTA + jg * KG + kg, 1u);
    }
}

// out[b][t][:] = Hall[t][b][:] @ wout   — one big tf32 GEMM, 32768 x 128 x 2048
__global__ void __launch_bounds__(256) out_gemm_kernel(
    const float* __restrict__ wout, float* __restrict__ out)
{
    __shared__ unsigned As[128 * 36];
    __shared__ unsigned Bs[32 * 132];
    const int tid  = threadIdx.x;
    const int lane = tid & 31, warp = tid >> 5;
    const int wm = warp >> 1, wn = warp & 1;
    const int m0w = wm * 32, n0w = wn * 64;
    const int hr0 = blockIdx.x * 128;   // Hall flat row = t*64 + b

    float4 acc[2][8];
    #pragma unroll
    for (int mt = 0; mt < 2; mt++)
        #pragma unroll
        for (int nt = 0; nt < 8; nt++) acc[mt][nt] = make_float4(0.f, 0.f, 0.f, 0.f);

    for (int k0 = 0; k0 < HH; k0 += 32) {
        for (int i4 = tid; i4 < 1024; i4 += 256) {
            int r = i4 >> 3, c4 = (i4 & 7) * 4;
            float4 v = *reinterpret_cast<const float4*>(
                g_Hall + (size_t)(hr0 + r) * HH + k0 + c4);
            uint4 u;
            u.x = f2tf32(v.x); u.y = f2tf32(v.y); u.z = f2tf32(v.z); u.w = f2tf32(v.w);
            *reinterpret_cast<uint4*>(As + r * 36 + c4) = u;
        }
        for (int i4 = tid; i4 < 1024; i4 += 256) {
            int k = i4 >> 5, o4 = (i4 & 31) * 4;
            float4 v = *reinterpret_cast<const float4*>(wout + (size_t)(k0 + k) * OO + o4);
            uint4 u;
            u.x = f2tf32(v.x); u.y = f2tf32(v.y); u.z = f2tf32(v.z); u.w = f2tf32(v.w);
            *reinterpret_cast<uint4*>(Bs + k * 132 + o4) = u;
        }
        __syncthreads();
        #pragma unroll
        for (int kk = 0; kk < 32; kk += 8) {
            unsigned a[2][4];
            #pragma unroll
            for (int mt = 0; mt < 2; mt++) {
                int row = m0w + mt * 16 + (lane >> 2);
                a[mt][0] = As[row * 36 + kk + (lane & 3)];
                a[mt][1] = As[(row + 8) * 36 + kk + (lane & 3)];
                a[mt][2] = As[row * 36 + kk + 4 + (lane & 3)];
                a[mt][3] = As[(row + 8) * 36 + kk + 4 + (lane & 3)];
            }
            #pragma unroll
            for (int nt = 0; nt < 8; nt++) {
                int col = n0w + nt * 8 + (lane >> 2);
                unsigned b0 = Bs[(kk + (lane & 3)) * 132 + col];
                unsigned b1 = Bs[(kk + 4 + (lane & 3)) * 132 + col];
                mma_tf32(acc[0][nt], a[0][0], a[0][1], a[0][2], a[0][3], b0, b1);
                mma_tf32(acc[1][nt], a[1][0], a[1][1], a[1][2], a[1][3], b0, b1);
            }
        }
        __syncthreads();
    }
    // write: Hall row hr = t*64+b  ->  out row b*512+t
    #pragma unroll
    for (int mt = 0; mt < 2; mt++) {
        int hr = hr0 + m0w + mt * 16 + (lane >> 2);
        #pragma unroll
        for (int half = 0; half < 2; half++) {
            int hrr = hr + half * 8;
            int b = hrr & (BB - 1), tt = hrr >> 6;
            float* orow = out + ((size_t)b * SS + tt) * OO;
            #pragma unroll
            for (int nt = 0; nt < 8; nt++) {
                int col = n0w + nt * 8 + (lane & 3) * 2;
                float2 v = half ? make_float2(acc[mt][nt].z, acc[mt][nt].w)
                                : make_float2(acc[mt][nt].x, acc[mt][nt].y);
                *reinterpret_cast<float2*>(orow + col) = v;
            }
        }
    }
}

extern "C" void kernel_launch(void* const* d_in, const int* in_sizes, int n_in,
                              void* d_out, int out_size) {
    const float* x     = (const float*)d_in[0];
    const float* noise = (const float*)d_in[1];
    const float* wi    = (const float*)d_in[2];
    const float* wrec  = (const float*)d_in[3];
    const float* wout  = (const float*)d_in[4];
    const float* g     = (const float*)d_in[5];
    const float* h0    = (const float*)d_in[6];
    float* out = (float*)d_out;

    size_t smem = (size_t)(NJ * WSP + BB * HSP + NJ * WXP + BB * XSP) * 4;  // 215040 B
    cudaFuncSetAttribute(rnn_step_kernel,
                         cudaFuncAttributeMaxDynamicSharedMemorySize, (int)smem);

    rnn_step_kernel<<<NCTA, 256, smem>>>(x, noise, wi, wrec, g, h0);
    out_gemm_kernel<<<(BB * SS) / 128, 256>>>(wout, out);
}